// round 13
// baseline (speedup 1.0000x reference)
#include <cuda_runtime.h>

// Problem constants (fixed by setup_inputs)
#define BATCH   16
#define CHAN    4
#define H_IN    128
#define W_IN    240
#define MAXD    24
#define H_OUT   1024
#define W_OUT   1920
#define W4      (W_OUT / 4)     // 480
#define HW      (H_IN * W_IN)
#define PAD     (MAXD - 1)      // 23 zero-pad float4s for negative shifts
#define TILE    8               // input rows per block
#define NROWS   (TILE + 1)      // + halo row
#define NTILES  (H_IN / TILE)   // 16
#define NTHREADS 512

// ---------------------------------------------------------------------------
// Fully fused kernel. One block per (batch, 8-input-row tile): 256 blocks,
// all co-resident (single wave). Phase A (FMA-bound disp) and Phase B
// (DRAM-bound resize) overlap ACROSS blocks on each SM.
//  Phase A: stage 9 zero-padded right rows (channel-packed float4) in smem,
//           compute 9 pred rows (cost volume + unshifted softmax) -> smem.
//  Phase B: thread-per-column-group resize; register pred window, hoisted
//           x-geometry, 512B-contiguous warp stores.
// ---------------------------------------------------------------------------
__global__ __launch_bounds__(NTHREADS, 3) void fused_kernel(
    const float* __restrict__ fl, const float* __restrict__ fr,
    float* __restrict__ out)
{
    const int blk = blockIdx.x;          // b*NTILES + ty
    const int b  = blk >> 4;
    const int ty = blk & (NTILES - 1);
    const int base_y = ty * TILE;
    const int tid = threadIdx.x;

    __shared__ float4 sr4[NROWS][PAD + W_IN];   // padded right rows
    __shared__ float  prow[NROWS][W_IN + 1];    // pred rows (+x pad)

    // ---- Phase A0: zero the pads ----
    for (int i = tid; i < NROWS * PAD; i += NTHREADS) {
        const int r = i / PAD;
        const int p = i - r * PAD;
        sr4[r][p] = make_float4(0.f, 0.f, 0.f, 0.f);
    }
    // ---- Phase A1: stage 9 right rows, channel-packed ----
    for (int i = tid; i < NROWS * CHAN * W_IN; i += NTHREADS) {   // 8640
        const int x = i % W_IN;
        const int t = i / W_IN;
        const int c = t & 3;
        const int r = t >> 2;
        const int yy = min(base_y + r, H_IN - 1);
        ((float*)&sr4[r][PAD + x])[c] =
            fr[(((size_t)b * CHAN + c) * H_IN + yy) * W_IN + x];
    }
    __syncthreads();

    // ---- Phase A2: disparity prediction, 9 rows x 240 px ----
    for (int i = tid; i < NROWS * W_IN; i += NTHREADS) {          // 2160
        const int r = i / W_IN;
        const int x = i - r * W_IN;
        const int yy = min(base_y + r, H_IN - 1);
        const size_t rb = (size_t)b * (CHAN * HW) + (size_t)yy * W_IN + x;
        float4 L;
        L.x = fl[rb];          L.y = fl[rb + HW];
        L.z = fl[rb + 2 * HW]; L.w = fl[rb + 3 * HW];

        const float4* __restrict__ rrow = &sr4[r][PAD + x];
        float num = 0.0f, den = 0.0f;
#pragma unroll
        for (int d = 0; d < MAXD; d++) {
            const float4 R = rrow[-d];            // pad keeps this in-bounds
            const float c = fabsf(L.x - R.x) + fabsf(L.y - R.y)
                          + fabsf(L.z - R.z) + fabsf(L.w - R.w);
            const float e = __expf(-c);           // softmax(-cost), unshifted
            den += e;
            num += (float)d * e;
        }
        prow[r][x] = (num / den) * 8.0f;          // * (1024/128)
    }
    __syncthreads();
    if (tid < NROWS) prow[tid][W_IN] = prow[tid][W_IN - 1];       // x pad
    __syncthreads();

    // ---- Phase B: bilinear upsample, thread-per-float4-column ----
    const int g = tid;
    if (g < W4) {
        const float xsc = 239.0f / 1919.0f;
        const float ysc = 127.0f / 1023.0f;

        // hoisted x-geometry for 4 contiguous output pixels
        const int ox0 = g * 4;
        const int q = (ox0 * 239) / 1919;         // exact base input cell
        float wx[4];
        bool  hi[4];
#pragma unroll
        for (int k = 0; k < 4; k++) {
            const float xf = (float)(ox0 + k) * xsc;
            const int x0 = (int)xf;
            wx[k] = xf - (float)x0;
            hi[k] = (x0 > q);                     // pixel lies in cell q+1
        }
        const int q1 = min(q + 1, W_IN - 1);
        const int q2 = min(q + 2, W_IN - 1);

        float4* __restrict__ out4 =
            (float4*)out + (size_t)b * H_OUT * W4 + g;

#pragma unroll
        for (int rl = 0; rl < TILE; rl++) {
            const int r = base_y + rl;
            const int oys = (r * (H_OUT - 1) + (H_IN - 2)) / (H_IN - 1);
            const int oye = min(H_OUT - 1,
                ((r + 1) * (H_OUT - 1) + (H_IN - 2)) / (H_IN - 1) - 1);

            // register-resident 2x3 pred window
            const float p00 = prow[rl][q], p01 = prow[rl][q1], p02 = prow[rl][q2];
            const float D0 = prow[rl + 1][q]  - p00;
            const float D1 = prow[rl + 1][q1] - p01;
            const float D2 = prow[rl + 1][q2] - p02;

            for (int oy = oys; oy <= oye; oy++) {
                const float wy = (float)oy * ysc - (float)r;
                const float v0 = p00 + wy * D0;   // y-lerp (3 FMA)
                const float v1 = p01 + wy * D1;
                const float v2 = p02 + wy * D2;
                const float d01 = v1 - v0;
                const float d12 = v2 - v1;

                float4 o;
#pragma unroll
                for (int k = 0; k < 4; k++) {
                    const float base = hi[k] ? v1 : v0;
                    const float del  = hi[k] ? d12 : d01;
                    ((float*)&o)[k] = base + wx[k] * del;
                }
                out4[(size_t)oy * W4] = o;        // warp: 512B contiguous
            }
        }
    }
}

extern "C" void kernel_launch(void* const* d_in, const int* in_sizes, int n_in,
                              void* d_out, int out_size)
{
    const float* feat_l = (const float*)d_in[0];
    const float* feat_r = (const float*)d_in[1];
    float* out = (float*)d_out;

    fused_kernel<<<BATCH * NTILES, NTHREADS>>>(feat_l, feat_r, out);
}